// round 2
// baseline (speedup 1.0000x reference)
#include <cuda_runtime.h>
#include <cstdint>

#define BOND_CUTOFF 3.6f

// ---------------------------------------------------------------------------
// Fused kernel: thresholded L1 distance matrix, reading positions directly
// from the stride-7 input (no pack pass).
// Block: 256 threads. Tile: TI=16 rows x TJ=2048 cols.
// Each thread owns 8 consecutive columns (2 float4 lanes), loops 16 rows,
// writes two coalesced float4 streaming stores per row.
// ---------------------------------------------------------------------------
#define TI 16
#define TJ 2048

__global__ __launch_bounds__(256, 6)
void graph_kernel(const float* __restrict__ x, float* __restrict__ out, int n) {
    const int t  = threadIdx.x;
    const int i0 = blockIdx.y * TI;

    // This thread's 8 columns: two groups of 4, strided so that each group's
    // 4 lanes are consecutive across the warp -> coalesced stores.
    //   group A cols: blockIdx.x*TJ + t*4            (t in [0,256))
    //   group B cols: blockIdx.x*TJ + 1024 + t*4
    const int jA = blockIdx.x * TJ + t * 4;
    const int jB = jA + 1024;

    // Load 8 column positions straight from the stride-7 input (once).
    float cx[8], cy[8], cz[8];
#pragma unroll
    for (int k = 0; k < 4; k++) {
        const float* p = x + (size_t)(jA + k) * 7;
        cx[k] = p[0]; cy[k] = p[1]; cz[k] = p[2];
    }
#pragma unroll
    for (int k = 0; k < 4; k++) {
        const float* p = x + (size_t)(jB + k) * 7;
        cx[4 + k] = p[0]; cy[4 + k] = p[1]; cz[4 + k] = p[2];
    }

    float* orowA = out + (size_t)i0 * n + jA;
    float* orowB = out + (size_t)i0 * n + jB;

#pragma unroll
    for (int r = 0; r < TI; r++) {
        // Broadcast load of row position (3 scalar L1-hit loads, 1 wf each).
        const float* pr = x + (size_t)(i0 + r) * 7;
        float px = pr[0], py = pr[1], pz = pr[2];

        float4 resA, resB;
        {
            float v[8];
#pragma unroll
            for (int k = 0; k < 8; k++) {
                float d = (fabsf(px - cx[k]) + fabsf(py - cy[k])) + fabsf(pz - cz[k]);
                v[k] = (d <= BOND_CUTOFF) ? 1.0f : 0.0f;
            }
            resA = make_float4(v[0], v[1], v[2], v[3]);
            resB = make_float4(v[4], v[5], v[6], v[7]);
        }

        // Streaming stores: output is write-once, never re-read -> evict-first.
        __stcs(reinterpret_cast<float4*>(orowA), resA);
        __stcs(reinterpret_cast<float4*>(orowB), resB);
        orowA += n;
        orowB += n;
    }
}

// ---------------------------------------------------------------------------
// Fallback for shapes that don't tile evenly (defensive; N=8192 does).
// ---------------------------------------------------------------------------
__global__ void graph_kernel_generic(const float* __restrict__ x,
                                     float* __restrict__ out, int n) {
    int j = blockIdx.x * blockDim.x + threadIdx.x;
    int i = blockIdx.y;
    if (i < n && j < n) {
        const float* pi = x + (size_t)i * 7;
        const float* pj = x + (size_t)j * 7;
        float d = (fabsf(pi[0] - pj[0]) + fabsf(pi[1] - pj[1])) + fabsf(pi[2] - pj[2]);
        out[(size_t)i * n + j] = (d <= BOND_CUTOFF) ? 1.0f : 0.0f;
    }
}

extern "C" void kernel_launch(void* const* d_in, const int* in_sizes, int n_in,
                              void* d_out, int out_size) {
    const float* x = (const float*)d_in[0];
    int n = in_sizes[0] / 7;
    float* out = (float*)d_out;

    if (n > 0 && (n % TJ) == 0 && (n % TI) == 0) {
        dim3 grid(n / TJ, n / TI);
        graph_kernel<<<grid, 256>>>(x, out, n);
    } else {
        dim3 grid((n + 255) / 256, n);
        graph_kernel_generic<<<grid, 256>>>(x, out, n);
    }
}

// round 3
// speedup vs baseline: 1.0119x; 1.0119x over previous
#include <cuda_runtime.h>
#include <cstdint>

#define BOND_CUTOFF 3.6f

// ---------------------------------------------------------------------------
// Fused kernel: thresholded L1 distance matrix on x[:, :3] of stride-7 input.
// Block: 256 threads. Tile: TI=32 rows x TJ=1024 cols.
// Each thread owns 4 consecutive columns (registers), loops 32 rows, emits
// one coalesced float4 store per row (32 chained STG.128 -> deep store MLP).
// ---------------------------------------------------------------------------
#define TI 32
#define TJ 1024

__global__ __launch_bounds__(256, 8)
void graph_kernel(const float* __restrict__ x, float* __restrict__ out, int n) {
    const int t  = threadIdx.x;
    const int i0 = blockIdx.y * TI;
    const int j0 = blockIdx.x * TJ + t * 4;   // this thread's 4 columns

    // One-time column position loads, straight from stride-7 input (L2-hot).
    float cx[4], cy[4], cz[4];
#pragma unroll
    for (int k = 0; k < 4; k++) {
        const float* p = x + (size_t)(j0 + k) * 7;
        cx[k] = p[0]; cy[k] = p[1]; cz[k] = p[2];
    }

    float* orow = out + (size_t)i0 * n + j0;

#pragma unroll
    for (int r = 0; r < TI; r++) {
        // Row position: 3 uniform-address broadcast loads (L1 hit).
        const float* pr = x + (size_t)(i0 + r) * 7;
        float px = pr[0], py = pr[1], pz = pr[2];

        float4 res;
        {
            float d0 = (fabsf(px - cx[0]) + fabsf(py - cy[0])) + fabsf(pz - cz[0]);
            float d1 = (fabsf(px - cx[1]) + fabsf(py - cy[1])) + fabsf(pz - cz[1]);
            float d2 = (fabsf(px - cx[2]) + fabsf(py - cy[2])) + fabsf(pz - cz[2]);
            float d3 = (fabsf(px - cx[3]) + fabsf(py - cy[3])) + fabsf(pz - cz[3]);
            res.x = (d0 <= BOND_CUTOFF) ? 1.0f : 0.0f;
            res.y = (d1 <= BOND_CUTOFF) ? 1.0f : 0.0f;
            res.z = (d2 <= BOND_CUTOFF) ? 1.0f : 0.0f;
            res.w = (d3 <= BOND_CUTOFF) ? 1.0f : 0.0f;
        }

        *reinterpret_cast<float4*>(orow) = res;
        orow += n;
    }
}

// ---------------------------------------------------------------------------
// Fallback for shapes that don't tile evenly (defensive; N=8192 does).
// ---------------------------------------------------------------------------
__global__ void graph_kernel_generic(const float* __restrict__ x,
                                     float* __restrict__ out, int n) {
    int j = blockIdx.x * blockDim.x + threadIdx.x;
    int i = blockIdx.y;
    if (i < n && j < n) {
        const float* pi = x + (size_t)i * 7;
        const float* pj = x + (size_t)j * 7;
        float d = (fabsf(pi[0] - pj[0]) + fabsf(pi[1] - pj[1])) + fabsf(pi[2] - pj[2]);
        out[(size_t)i * n + j] = (d <= BOND_CUTOFF) ? 1.0f : 0.0f;
    }
}

extern "C" void kernel_launch(void* const* d_in, const int* in_sizes, int n_in,
                              void* d_out, int out_size) {
    const float* x = (const float*)d_in[0];
    int n = in_sizes[0] / 7;
    float* out = (float*)d_out;

    if (n > 0 && (n % TJ) == 0 && (n % TI) == 0) {
        dim3 grid(n / TJ, n / TI);
        graph_kernel<<<grid, 256>>>(x, out, n);
    } else {
        dim3 grid((n + 255) / 256, n);
        graph_kernel_generic<<<grid, 256>>>(x, out, n);
    }
}